// round 6
// baseline (speedup 1.0000x reference)
#include <cuda_runtime.h>
#include <math.h>
#include <stdint.h>

#define B_   32
#define T_   512
#define E_   256
#define H_   512
#define NG   2048
#define NBLK 128

__device__ __align__(16) float  g_xWx  [(size_t)T_ * B_ * NG];
__device__ __align__(16) float  g_fcore[(size_t)T_ * B_ * 192];
__device__ __align__(16) float  g_revxw[(size_t)T_ * B_ * 40];
__device__ __align__(16) float2 g_d    [T_ * B_];
__device__ __align__(16) float  g_h    [2][B_ * H_];
__device__ unsigned g_cnt;
__device__ unsigned g_gen;

__device__ __forceinline__ float sigf(float x) { return 1.f / (1.f + expf(-x)); }

// ------------------- init: zero h, reset barrier -------------------
__global__ void k_init() {
    int i = blockIdx.x * blockDim.x + threadIdx.x;
    if (i < B_ * H_) g_h[0][i] = 0.f;
    if (i == 0) { g_cnt = 0; *(volatile unsigned*)&g_gen = 0u; }
}

// ------------------- xWx GEMM: M=16384 N=2048 K=256 -------------------
__global__ void __launch_bounds__(256) k_xwx(const float* __restrict__ x,
                                             const float* __restrict__ Wx,
                                             const float* __restrict__ bias)
{
    __shared__ __align__(16) float a_sh[8][128];
    __shared__ __align__(16) float b_sh[8][128];
    const int n0 = blockIdx.x * 128;
    const int m0 = blockIdx.y * 128;
    const int tid = threadIdx.x;
    const int ty8 = (tid >> 4) * 8;
    const int tx8 = (tid & 15) * 8;

    float acc[8][8];
#pragma unroll
    for (int i = 0; i < 8; ++i)
#pragma unroll
        for (int j = 0; j < 8; ++j) acc[i][j] = 0.f;

    const int arow = tid >> 1;
    const int akq  = (tid & 1) * 4;
    const int m    = m0 + arow;
    const int bb   = m & 31;
    const int tt   = m >> 5;
    const float* aptr = x + ((size_t)bb * T_ + tt) * E_ + akq;
    const int bkk = tid >> 5;
    const int bnq = (tid & 31) * 4;

    for (int k0 = 0; k0 < E_; k0 += 8) {
        float4 av = *(const float4*)(aptr + k0);
        a_sh[akq + 0][arow] = av.x;
        a_sh[akq + 1][arow] = av.y;
        a_sh[akq + 2][arow] = av.z;
        a_sh[akq + 3][arow] = av.w;
        *(float4*)&b_sh[bkk][bnq] = *(const float4*)(Wx + (size_t)(k0 + bkk) * NG + n0 + bnq);
        __syncthreads();
#pragma unroll
        for (int k = 0; k < 8; ++k) {
            float af[8], bf[8];
            *(float4*)(af)     = *(const float4*)&a_sh[k][ty8];
            *(float4*)(af + 4) = *(const float4*)&a_sh[k][ty8 + 4];
            *(float4*)(bf)     = *(const float4*)&b_sh[k][tx8];
            *(float4*)(bf + 4) = *(const float4*)&b_sh[k][tx8 + 4];
#pragma unroll
            for (int i = 0; i < 8; ++i)
#pragma unroll
                for (int j = 0; j < 8; ++j)
                    acc[i][j] = fmaf(af[i], bf[j], acc[i][j]);
        }
        __syncthreads();
    }
#pragma unroll
    for (int i = 0; i < 8; ++i) {
        float* cp = g_xWx + (size_t)(m0 + ty8 + i) * NG + n0 + tx8;
#pragma unroll
        for (int j = 0; j < 8; ++j) acc[i][j] += bias[n0 + tx8 + j];
        *(float4*)cp       = make_float4(acc[i][0], acc[i][1], acc[i][2], acc[i][3]);
        *(float4*)(cp + 4) = make_float4(acc[i][4], acc[i][5], acc[i][6], acc[i][7]);
    }
}

// ------------------- convs -> g_fcore[..][0..180) -------------------
__global__ void __launch_bounds__(192) k_conv(const float* __restrict__ x,
        const float* __restrict__ w1, const float* __restrict__ b1,
        const float* __restrict__ w2, const float* __restrict__ b2,
        const float* __restrict__ w3, const float* __restrict__ b3)
{
    __shared__ float xs[8][256];
    const int t0 = blockIdx.x * 4;
    const int b  = blockIdx.y;
    const int tid = threadIdx.x;

    for (int i = tid; i < 8 * 256; i += 192) {
        int r = i >> 8, e = i & 255;
        int t = t0 - 2 + r;
        xs[r][e] = (t >= 0 && t < T_) ? x[((size_t)b * T_ + t) * E_ + e] : 0.f;
    }
    __syncthreads();
    if (tid >= 180) return;

    const int tloc = tid / 45;
    const int grp  = tid % 45;
    const float* w; const float* bias; int K, pl, cbase, c4;
    if (grp < 15)      { w = w1; bias = b1; K = 3; pl = 1; cbase = 0;   c4 = grp * 4; }
    else if (grp < 30) { w = w2; bias = b2; K = 4; pl = 1; cbase = 60;  c4 = (grp - 15) * 4; }
    else               { w = w3; bias = b3; K = 5; pl = 2; cbase = 120; c4 = (grp - 30) * 4; }

    float4 acc = make_float4(bias[c4], bias[c4 + 1], bias[c4 + 2], bias[c4 + 3]);
    for (int dt = 0; dt < K; ++dt) {
        const int r = tloc + dt - pl + 2;
        const float* wp = w + (size_t)dt * E_ * 60 + c4;
#pragma unroll 4
        for (int e = 0; e < E_; ++e) {
            float xv = xs[r][e];
            float4 wv = *(const float4*)(wp + (size_t)e * 60);
            acc.x = fmaf(xv, wv.x, acc.x);
            acc.y = fmaf(xv, wv.y, acc.y);
            acc.z = fmaf(xv, wv.z, acc.z);
            acc.w = fmaf(xv, wv.w, acc.w);
        }
    }
    const int t = t0 + tloc;
    *(float4*)&g_fcore[((size_t)t * B_ + b) * 192 + cbase + c4] = acc;
}

// ------------------- rev-LSTM input projection -------------------
__global__ void __launch_bounds__(320) k_revxw(const float* __restrict__ x,
                                               const float* __restrict__ Wx)
{
    __shared__ float xr[32][256];
    const int s = blockIdx.x, tid = threadIdx.x;
    const int t = T_ - 1 - s;
    for (int i = tid; i < 32 * 256; i += 320) {
        int b = i >> 8, e = i & 255;
        xr[b][e] = x[((size_t)b * T_ + t) * E_ + e];
    }
    __syncthreads();
    const int b = tid / 10, j = tid % 10;
    float a0 = 0.f, a1 = 0.f, a2 = 0.f, a3 = 0.f;
#pragma unroll 4
    for (int e = 0; e < 256; ++e) {
        float xv = xr[b][e];
        const float* wp = Wx + (size_t)e * 40 + j;
        a0 = fmaf(xv, __ldg(wp),      a0);
        a1 = fmaf(xv, __ldg(wp + 10), a1);
        a2 = fmaf(xv, __ldg(wp + 20), a2);
        a3 = fmaf(xv, __ldg(wp + 30), a3);
    }
    float* dst = &g_revxw[((size_t)s * B_ + b) * 40 + j];
    dst[0] = a0; dst[10] = a1; dst[20] = a2; dst[30] = a3;
}

// ------------------- rev-LSTM scan (single block) -------------------
__global__ void __launch_bounds__(320) k_revscan(const float* __restrict__ Wh,
                                                 const float* __restrict__ bias)
{
    __shared__ float h[320];
    __shared__ float wsh[400];
    const int tid = threadIdx.x;
    for (int i = tid; i < 400; i += 320) wsh[i] = Wh[i];
    h[tid] = 0.f;
    const int b = tid / 10, j = tid % 10;
    const float bi = bias[j], bf = bias[10 + j], bg = bias[20 + j], bo = bias[30 + j];
    float c = 0.f;
    __syncthreads();
    for (int s = 0; s < T_; ++s) {
        const float* zx = &g_revxw[((size_t)s * B_ + b) * 40];
        float zi = zx[j] + bi, zf = zx[10 + j] + bf, zg = zx[20 + j] + bg, zo = zx[30 + j] + bo;
#pragma unroll
        for (int p = 0; p < 10; ++p) {
            float hv = h[b * 10 + p];
            zi = fmaf(hv, wsh[p * 40 + j],      zi);
            zf = fmaf(hv, wsh[p * 40 + 10 + j], zf);
            zg = fmaf(hv, wsh[p * 40 + 20 + j], zg);
            zo = fmaf(hv, wsh[p * 40 + 30 + j], zo);
        }
        c = sigf(zf) * c + sigf(zi) * tanhf(zg);
        float hn = sigf(zo) * tanhf(c);
        __syncthreads();
        h[tid] = hn;
        g_fcore[((size_t)s * B_ + b) * 192 + 180 + j] = hn;
        __syncthreads();
    }
}

// ------------------- gate MLP -> g_d (8 pairs per block) -------------------
__global__ void __launch_bounds__(128) k_gate(const float* __restrict__ x,
        const float* __restrict__ d0W, const float* __restrict__ d0b,
        const float* __restrict__ d1W, const float* __restrict__ d1b,
        const float* __restrict__ gn)
{
    __shared__ float in_sh[8][448];
    __shared__ float hid_sh[8][100];
    const int q0 = blockIdx.x * 8;
    const int tid = threadIdx.x;
    for (int i = tid; i < 8 * 448; i += 128) {
        int u = i / 448, e = i % 448;
        int q = q0 + u, t = q >> 5, b = q & 31;
        float v = 0.f;
        if (e < 190) { if (t < T_ - 1) v = g_fcore[((size_t)(t + 1) * B_ + b) * 192 + e]; }
        else if (e < 446) v = x[((size_t)b * T_ + t) * E_ + (e - 190)];
        in_sh[u][e] = v;
    }
    __syncthreads();
    if (tid < 100) {
        float acc[8];
#pragma unroll
        for (int u = 0; u < 8; ++u) acc[u] = d0b[tid];
        for (int e = 0; e < 446; ++e) {
            float w = d0W[(size_t)e * 100 + tid];
#pragma unroll
            for (int u = 0; u < 8; ++u) acc[u] = fmaf(in_sh[u][e], w, acc[u]);
        }
#pragma unroll
        for (int u = 0; u < 8; ++u) hid_sh[u][tid] = fmaxf(acc[u], 0.f);
    }
    __syncthreads();
    if (tid < 8) {
        const int u = tid, q = q0 + u, t = q >> 5, b = q & 31;
        float p0 = d1b[0], p1 = d1b[1];
        for (int j = 0; j < 100; ++j) {
            float hv = hid_sh[u][j];
            p0 = fmaf(hv, d1W[2 * j],     p0);
            p1 = fmaf(hv, d1W[2 * j + 1], p1);
        }
        float a0 = (p0 + gn[((size_t)t * B_ + b) * 2])     / 1e-5f;
        float a1 = (p1 + gn[((size_t)t * B_ + b) * 2 + 1]) / 1e-5f;
        float mx = fmaxf(a0, a1);
        float e0 = expf(a0 - mx), e1 = expf(a1 - mx);
        float s = e0 + e1;
        g_d[q] = make_float2(e0 / s, e1 / s);
    }
}

// ------------------- main persistent scan -------------------
__global__ void __launch_bounds__(256, 1) k_scan(const float* __restrict__ Wh,
                                                 float* __restrict__ out)
{
    extern __shared__ float sm[];
    float* w_sh = sm;                 // [16][512]
    float* h_sh = sm + 16 * 512;      // [32][512]
    float* z_sh = h_sh + 32 * 512;    // [32][16]
    const int tid  = threadIdx.x;
    const int nb   = blockIdx.x;
    const int bgrp = tid >> 5;        // warp id, 0..7 -> 4 batches each
    const int lane = tid & 31;
    const int cgrp = lane >> 3;       // 0..3 -> 4 cols each
    const int ks   = lane & 7;        // 0..7 k-split

    // load 16 Wh columns (col c: gate=c>>2, hh=c&3, n = gate*512 + nb*4 + hh)
    for (int idx = tid; idx < 16 * 512; idx += 256) {
        int c = idx >> 9, k = idx & 511;
        int n = (c >> 2) * 512 + nb * 4 + (c & 3);
        w_sh[c * 512 + k] = Wh[(size_t)k * NG + n];
    }

    const int cb = tid >> 2;          // combine thread batch (tid<128)
    const int hh = tid & 3;
    const int hglob = nb * 4 + hh;
    float cst = 0.f;

    for (int t = 0; t < T_; ++t) {
        const int cur = t & 1;
        const float* hg = g_h[cur];
        for (int i = tid; i < (B_ * H_) / 4; i += 256)
            ((float4*)h_sh)[i] = __ldcg(((const float4*)hg) + i);

        float4 zx; float2 dv;
        if (tid < 128) {
            const float* xw = g_xWx + ((size_t)t * B_ + cb) * NG + hglob;
            zx.x = __ldg(xw);
            zx.y = __ldg(xw + 512);
            zx.z = __ldg(xw + 1024);
            zx.w = __ldg(xw + 1536);
            dv = g_d[t * B_ + cb];
        }
        __syncthreads();

        float acc[4][4];
#pragma unroll
        for (int i = 0; i < 4; ++i)
#pragma unroll
            for (int j = 0; j < 4; ++j) acc[i][j] = 0.f;

        const float* hp = h_sh + (bgrp * 4) * 512 + ks * 4;
        const float* wp = w_sh + (cgrp * 4) * 512 + ks * 4;
#pragma unroll 4
        for (int it = 0; it < 16; ++it) {
            const int ko = it * 32;
            float4 hv[4], wv[4];
#pragma unroll
            for (int bi = 0; bi < 4; ++bi) hv[bi] = *(const float4*)(hp + bi * 512 + ko);
#pragma unroll
            for (int ci = 0; ci < 4; ++ci) wv[ci] = *(const float4*)(wp + ci * 512 + ko);
#pragma unroll
            for (int bi = 0; bi < 4; ++bi)
#pragma unroll
                for (int ci = 0; ci < 4; ++ci) {
                    acc[bi][ci] = fmaf(hv[bi].x, wv[ci].x, acc[bi][ci]);
                    acc[bi][ci] = fmaf(hv[bi].y, wv[ci].y, acc[bi][ci]);
                    acc[bi][ci] = fmaf(hv[bi].z, wv[ci].z, acc[bi][ci]);
                    acc[bi][ci] = fmaf(hv[bi].w, wv[ci].w, acc[bi][ci]);
                }
        }
#pragma unroll
        for (int off = 4; off; off >>= 1)
#pragma unroll
            for (int bi = 0; bi < 4; ++bi)
#pragma unroll
                for (int ci = 0; ci < 4; ++ci)
                    acc[bi][ci] += __shfl_xor_sync(0xffffffffu, acc[bi][ci], off);
        if (ks == 0) {
#pragma unroll
            for (int bi = 0; bi < 4; ++bi)
#pragma unroll
                for (int ci = 0; ci < 4; ++ci)
                    z_sh[(bgrp * 4 + bi) * 16 + cgrp * 4 + ci] = acc[bi][ci];
        }
        __syncthreads();

        if (tid < 128) {
            float zi = z_sh[cb * 16 + 0  + hh] + zx.x;
            float zf = z_sh[cb * 16 + 4  + hh] + zx.y;
            float zg = z_sh[cb * 16 + 8  + hh] + zx.z;
            float zo = z_sh[cb * 16 + 12 + hh] + zx.w;
            float ccand = sigf(zf) * cst + sigf(zi) * tanhf(zg);
            float hcand = sigf(zo) * tanhf(ccand);
            out[(size_t)cb * (T_ * H_) + (size_t)t * H_ + hglob] = hcand;
            float hold = h_sh[cb * 512 + hglob];
            float hnew = dv.x * hcand + dv.y * hold;
            cst = dv.x * ccand + dv.y * cst;
            g_h[1 - cur][cb * 512 + hglob] = hnew;
        }
        __syncthreads();
        __threadfence();
        if (tid == 0) {
            unsigned a = atomicAdd(&g_cnt, 1u);
            if (a == NBLK - 1) {
                g_cnt = 0;
                __threadfence();
                *(volatile unsigned*)&g_gen = (unsigned)(t + 1);
            } else {
                while (*(volatile unsigned*)&g_gen < (unsigned)(t + 1)) __nanosleep(32);
                __threadfence();
            }
        }
        __syncthreads();
    }
}

extern "C" void kernel_launch(void* const* d_in, const int* in_sizes, int n_in,
                              void* d_out, int out_size) {
    const float* x   = (const float*)d_in[0];
    const float* c1w = (const float*)d_in[1];
    const float* c1b = (const float*)d_in[2];
    const float* c2w = (const float*)d_in[3];
    const float* c2b = (const float*)d_in[4];
    const float* c3w = (const float*)d_in[5];
    const float* c3b = (const float*)d_in[6];
    const float* rWx = (const float*)d_in[7];
    const float* rWh = (const float*)d_in[8];
    const float* rb  = (const float*)d_in[9];
    const float* d0W = (const float*)d_in[10];
    const float* d0b = (const float*)d_in[11];
    const float* d1W = (const float*)d_in[12];
    const float* d1b = (const float*)d_in[13];
    const float* cWx = (const float*)d_in[14];
    const float* cWh = (const float*)d_in[15];
    const float* cb  = (const float*)d_in[16];
    const float* gn  = (const float*)d_in[17];
    float* out = (float*)d_out;

    static int smem_set = 0;
    const int SMEM = (16 * 512 + 32 * 512 + 32 * 16) * 4;
    if (!smem_set) {
        cudaFuncSetAttribute(k_scan, cudaFuncAttributeMaxDynamicSharedMemorySize, SMEM);
        smem_set = 1;
    }

    k_init<<<32, 512>>>();
    k_xwx<<<dim3(16, 128), 256>>>(x, cWx, cb);
    k_conv<<<dim3(T_ / 4, B_), 192>>>(x, c1w, c1b, c2w, c2b, c3w, c3b);
    k_revxw<<<T_, 320>>>(x, rWx);
    k_revscan<<<1, 320>>>(rWh, rb);
    k_gate<<<(T_ * B_) / 8, 128>>>(x, d0W, d0b, d1W, d1b, gn);
    k_scan<<<NBLK, 256, SMEM>>>(cWh, out);
}